// round 17
// baseline (speedup 1.0000x reference)
#include <cuda_runtime.h>
#include <cuda_fp16.h>

#define NG 128
#define FEAT 16
#define WIDTH 64
#define NUM_POS 3
#define IN_MLP 25          // FEAT + NUM_POS*3 (padded to 28 in smem)
#define INP 28             // padded input count (x4-tileable)
#define GRID_ELEMS (NG*NG*NG*FEAT)   // 33,554,432
#define CONV_UNITS 16384             // 2048 elems per unit
#define UNITS_PER_PLANE 128

// fp16 copy of the grid: 64 MB -> L2-resident (L2 = 126 MB).
__device__ __half g_grid_h[GRID_ELEMS];
__device__ int g_plane_done[NG];     // convert units completed per x-plane
__device__ int g_unit_next;          // global convert work queue head

// ---- packed f32x2 helpers (sm_10x) ----
__device__ __forceinline__ unsigned long long pack2(float a, float b) {
    unsigned long long r;
    asm("mov.b64 %0, {%1, %2};" : "=l"(r) : "f"(a), "f"(b));
    return r;
}
__device__ __forceinline__ void unpack2(unsigned long long v, float& a, float& b) {
    asm("mov.b64 {%0, %1}, %2;" : "=f"(a), "=f"(b) : "l"(v));
}
__device__ __forceinline__ unsigned long long fma2(unsigned long long a,
                                                   unsigned long long b,
                                                   unsigned long long c) {
    unsigned long long d;
    asm("fma.rn.f32x2 %0, %1, %2, %3;" : "=l"(d) : "l"(a), "l"(b), "l"(c));
    return d;
}
__device__ __forceinline__ unsigned long long add2(unsigned long long a,
                                                   unsigned long long b) {
    unsigned long long d;
    asm("add.rn.f32x2 %0, %1, %2;" : "=l"(d) : "l"(a), "l"(b));
    return d;
}
__device__ __forceinline__ unsigned h2u(__half2 h) {
    return *reinterpret_cast<unsigned*>(&h);
}
__device__ __forceinline__ int ldacq(const int* p) {
    int v;
    asm volatile("ld.acquire.gpu.global.b32 %0, [%1];" : "=r"(v) : "l"(p));
    return v;
}
// packed reduce over lane bits 1,2 (64-bit shfl + packed add)
__device__ __forceinline__ unsigned long long redc2(unsigned long long v) {
    v = add2(v, __shfl_xor_sync(0xFFFFFFFFu, v, 2));
    v = add2(v, __shfl_xor_sync(0xFFFFFFFFu, v, 4));
    return v;
}

__device__ __forceinline__ void cubic_w(float t, float w[4]) {
    float t2 = t * t, t3 = t2 * t;
    w[0] = 0.5f * (-t3 + 2.0f * t2 - t);
    w[1] = 0.5f * (3.0f * t3 - 5.0f * t2 + 2.0f);
    w[2] = 0.5f * (-3.0f * t3 + 4.0f * t2 + t);
    w[3] = 0.5f * (t3 - t2);
}

// Warp-collective: convert one 2048-elem unit pulled from the global queue.
// Returns immediately (after a nanosleep) if the queue is drained.
__device__ __forceinline__ void convert_one_unit(const float* __restrict__ grid,
                                                 int lane) {
    int c = 0;
    if (lane == 0) c = atomicAdd(&g_unit_next, 1);
    c = __shfl_sync(0xFFFFFFFFu, c, 0);
    if (c < CONV_UNITS) {
        #pragma unroll
        for (int it = 0; it < 8; it++) {
            int idx8 = c * 256 + it * 32 + lane;     // 8-elem groups
            const float4* src = reinterpret_cast<const float4*>(grid)
                                + (size_t)idx8 * 2;
            float4 a = __ldcs(src);
            float4 b = __ldcs(src + 1);
            uint4 o;
            o.x = h2u(__floats2half2_rn(a.x, a.y));
            o.y = h2u(__floats2half2_rn(a.z, a.w));
            o.z = h2u(__floats2half2_rn(b.x, b.y));
            o.w = h2u(__floats2half2_rn(b.z, b.w));
            reinterpret_cast<uint4*>(g_grid_h)[idx8] = o;
        }
        __threadfence();
        if (lane == 0) atomicAdd(&g_plane_done[c >> 7], 1);
    } else {
        __nanosleep(256);
    }
}

// ============ reset: zero convert-progress state ============
__global__ void reset_kernel() {
    if (threadIdx.x < NG) g_plane_done[threadIdx.x] = 0;
    if (threadIdx.x == 0) g_unit_next = 0;
}

// ============ mega: fused gather/MLP whose waits DO the conversion ============
__global__ __launch_bounds__(256, 4) void mega_kernel(
    const float* __restrict__ x,
    const float* __restrict__ grid,
    const float* __restrict__ w1,
    const float* __restrict__ b1,
    const float* __restrict__ w2,
    const float* __restrict__ b2,
    float* __restrict__ out,
    int npts)
{
    __shared__ ulonglong2 s_wu[INP][16];         // padded: rows 25..27 zero
    __shared__ ulonglong2 s_bu[16];
    __shared__ ulonglong2 s_w2u[16];
    __shared__ float s_b2;
    __shared__ __align__(16) float s_h[8][8][INP];   // [warp][pt-in-warp][input]

    for (int e = threadIdx.x; e < INP * 16; e += 256) {
        int i = e >> 4, uq = e & 15;
        ulonglong2 v;
        if (i < IN_MLP) {
            v.x = pack2(w1[uq * IN_MLP + i],        w1[(uq + 16) * IN_MLP + i]);
            v.y = pack2(w1[(uq + 32) * IN_MLP + i], w1[(uq + 48) * IN_MLP + i]);
        } else {
            v.x = 0ull; v.y = 0ull;
        }
        s_wu[i][uq] = v;
    }
    if (threadIdx.x < 16) {
        int uq = threadIdx.x;
        ulonglong2 bv, wv;
        bv.x = pack2(b1[uq],      b1[uq + 16]);
        bv.y = pack2(b1[uq + 32], b1[uq + 48]);
        wv.x = pack2(w2[uq],      w2[uq + 16]);
        wv.y = pack2(w2[uq + 32], w2[uq + 48]);
        s_bu[uq]  = bv;
        s_w2u[uq] = wv;
    }
    if (threadIdx.x == 0) s_b2 = b2[0];
    for (int e = threadIdx.x; e < 8 * 8 * 3; e += 256) {
        int w = e / 24, r = e % 24;
        s_h[w][r / 3][IN_MLP + (r % 3)] = 0.0f;
    }
    __syncthreads();

    int warpId = threadIdx.x >> 5;
    int lane   = threadIdx.x & 31;
    int g      = lane >> 3;          // gather group 0..3
    int sub    = lane & 7;
    int c      = sub >> 1;           // z-tap 0..3
    int fh     = sub & 1;            // feature half 0..1
    int foff   = fh * 8;
    int uq     = lane & 15;          // unit quad 0..15
    int pq     = lane >> 4;          // point quad 0..1

    int p_base = blockIdx.x * 64 + warpId * 8;   // this warp's 8 points
    int pg0 = p_base + 2 * g;        // gather group's two points

    const unsigned m = 0xFFFFFFFFu;
    int pk = sub / 3;
    int pd = sub - 3 * pk;
    const float TWO_PI = 6.283185307179586f;

    // -------- gather (fp16 grid), two points, convert-helping waits --------
    #pragma unroll
    for (int p = 0; p < 2; p++) {
        int ptp = pg0 + p;
        int ptc = (ptp < npts) ? ptp : npts - 1;
        float ux = __ldg(&x[3 * ptc + 0]) * 127.0f;
        float uy = __ldg(&x[3 * ptc + 1]) * 127.0f;
        float uz = __ldg(&x[3 * ptc + 2]) * 127.0f;
        float fx = floorf(ux), fy = floorf(uy), fz = floorf(uz);
        float tx = ux - fx, ty = uy - fy, tz = uz - fz;
        int ix0 = (int)fx, iy0 = (int)fy, iz0 = (int)fz;

        // Warp-collective wait for the 4 groups' current points' x-planes.
        // Lane sub checks one of its group's <=4 planes; while any lane's
        // plane is unready, the WHOLE warp converts a unit (useful work).
        {
            int myplane = min(max(ix0 - 1 + (sub & 3), 0), NG - 1);
            while (true) {
                bool rdy = (ldacq(&g_plane_done[myplane]) >= UNITS_PER_PLANE);
                if (__all_sync(m, rdy)) break;
                convert_one_unit(grid, lane);
            }
        }

        float wx[4], wy[4], wz[4];
        cubic_w(tx, wx);
        cubic_w(ty, wy);
        cubic_w(tz, wz);
        float wzc = wz[c];
        int zi = min(max(iz0 + c - 1, 0), NG - 1);

        unsigned long long a01 = 0, a23 = 0, a45 = 0, a67 = 0;
        #pragma unroll
        for (int a = 0; a < 4; a++) {
            int xi = min(max(ix0 + a - 1, 0), NG - 1);
            const __half* gx = g_grid_h + (size_t)xi * (NG * NG * FEAT);
            float wxa = wx[a];
            #pragma unroll
            for (int b = 0; b < 4; b++) {
                int yi = min(max(iy0 + b - 1, 0), NG - 1);
                float w = wxa * wy[b] * wzc;
                unsigned long long wp = pack2(w, w);
                const uint4* gp = reinterpret_cast<const uint4*>(
                    gx + (yi * NG + zi) * FEAT + foff);
                uint4 raw = __ldg(gp);
                float2 f0 = __half22float2(*reinterpret_cast<__half2*>(&raw.x));
                float2 f1 = __half22float2(*reinterpret_cast<__half2*>(&raw.y));
                float2 f2 = __half22float2(*reinterpret_cast<__half2*>(&raw.z));
                float2 f3 = __half22float2(*reinterpret_cast<__half2*>(&raw.w));
                a01 = fma2(wp, pack2(f0.x, f0.y), a01);
                a23 = fma2(wp, pack2(f1.x, f1.y), a23);
                a45 = fma2(wp, pack2(f2.x, f2.y), a45);
                a67 = fma2(wp, pack2(f3.x, f3.y), a67);
            }
        }
        a01 = redc2(a01);  a23 = redc2(a23);
        a45 = redc2(a45);  a67 = redc2(a67);

        int pw = 2 * g + p;                    // point slot within warp
        if (sub < 2) {                          // c==0 lanes; sub == fh
            float* row = s_h[warpId][pw];
            ulonglong2 v0, v1;
            v0.x = a01;  v0.y = a23;
            v1.x = a45;  v1.y = a67;
            *reinterpret_cast<ulonglong2*>(&row[sub * 8 + 0]) = v0;
            *reinterpret_cast<ulonglong2*>(&row[sub * 8 + 4]) = v1;
        }
        float t3v = (pd == 0) ? tx : (pd == 1) ? ty : tz;
        s_h[warpId][pw][FEAT + sub] = __sinf(TWO_PI * (float)(pk + 1) * t3v);
        if (sub == 0)
            s_h[warpId][pw][FEAT + 8] = __sinf(TWO_PI * 3.0f * tz);
    }
    __syncwarp();

    // -------- MLP: 4 units x 4 points per lane, h via LDS.128 --------
    ulonglong2 bu = s_bu[uq];
    unsigned long long q01[4], q23[4];   // units (uq,uq+16) / (uq+32,uq+48)
    #pragma unroll
    for (int j = 0; j < 4; j++) { q01[j] = bu.x; q23[j] = bu.y; }

    #pragma unroll
    for (int i4 = 0; i4 < INP; i4 += 4) {
        ulonglong2 w0  = s_wu[i4 + 0][uq];
        ulonglong2 wv1 = s_wu[i4 + 1][uq];
        ulonglong2 wv2 = s_wu[i4 + 2][uq];
        ulonglong2 wv3 = s_wu[i4 + 3][uq];
        #pragma unroll
        for (int j = 0; j < 4; j++) {
            float4 hv = *reinterpret_cast<const float4*>(
                &s_h[warpId][pq * 4 + j][i4]);
            unsigned long long h0  = pack2(hv.x, hv.x);
            unsigned long long h1  = pack2(hv.y, hv.y);
            unsigned long long h2p = pack2(hv.z, hv.z);
            unsigned long long h3  = pack2(hv.w, hv.w);
            q01[j] = fma2(w0.x,  h0,  q01[j]);
            q23[j] = fma2(w0.y,  h0,  q23[j]);
            q01[j] = fma2(wv1.x, h1,  q01[j]);
            q23[j] = fma2(wv1.y, h1,  q23[j]);
            q01[j] = fma2(wv2.x, h2p, q01[j]);
            q23[j] = fma2(wv2.y, h2p, q23[j]);
            q01[j] = fma2(wv3.x, h3,  q01[j]);
            q23[j] = fma2(wv3.y, h3,  q23[j]);
        }
    }

    // -------- epilogue: swish, w2 dot, reduce over 16 uq lanes --------
    ulonglong2 w2u = s_w2u[uq];
    float w2a, w2b, w2c, w2d;
    unpack2(w2u.x, w2a, w2b);
    unpack2(w2u.y, w2c, w2d);

    float l0 = 0.f, l1 = 0.f, l2 = 0.f, l3 = 0.f;
    #pragma unroll
    for (int j = 0; j < 4; j++) {
        float s0, s1, s2, s3;
        unpack2(q01[j], s0, s1);
        unpack2(q23[j], s2, s3);
        float r0 = s0 * __fdividef(1.0f, 1.0f + __expf(-s0));
        float r1 = s1 * __fdividef(1.0f, 1.0f + __expf(-s1));
        float r2 = s2 * __fdividef(1.0f, 1.0f + __expf(-s2));
        float r3 = s3 * __fdividef(1.0f, 1.0f + __expf(-s3));
        float lv = w2a * r0 + w2b * r1 + w2c * r2 + w2d * r3;
        lv += __shfl_xor_sync(m, lv, 1);
        lv += __shfl_xor_sync(m, lv, 2);
        lv += __shfl_xor_sync(m, lv, 4);
        lv += __shfl_xor_sync(m, lv, 8);
        if (j == 0) l0 = lv; else if (j == 1) l1 = lv;
        else if (j == 2) l2 = lv; else l3 = lv;
    }

    if (uq < 4) {
        int pw = p_base + pq * 4 + uq;
        if (pw < npts) {
            float res = (uq == 0) ? l0 : (uq == 1) ? l1 : (uq == 2) ? l2 : l3;
            out[pw] = res + s_b2;
        }
    }
}

extern "C" void kernel_launch(void* const* d_in, const int* in_sizes, int n_in,
                              void* d_out, int out_size) {
    const float* x    = (const float*)d_in[0];
    const float* grid = (const float*)d_in[1];
    const float* w1   = (const float*)d_in[2];
    const float* b1   = (const float*)d_in[3];
    const float* w2   = (const float*)d_in[4];
    const float* b2   = (const float*)d_in[5];
    float* out = (float*)d_out;

    int npts = in_sizes[0] / 3;

    reset_kernel<<<1, 128>>>();

    int blocks = (npts + 63) / 64;   // 64 points per 256-thread block
    mega_kernel<<<blocks, 256>>>(x, grid, w1, b1, w2, b2, out, npts);
}